// round 12
// baseline (speedup 1.0000x reference)
#include <cuda_runtime.h>
#include <cuda_bf16.h>
#include <math.h>
#include <stdint.h>

#define HDIM   1024
#define TSTEPS 256
#define VOCAB  50257

// ---------------- recurrence config (R11 WIN, untouched) ----------------
#define RNN_NB      64
#define RNN_THREADS 256
#define VEC_PER_BLK 3
#define NVEC        (RNN_NB * VEC_PER_BLK)   // 192
#define VEC_STRIDE  8                        // 128B per vector

// -------- device scratch --------
__device__ __align__(16)  __nv_bfloat16 g_Hb[TSTEPS * HDIM];
__device__ __align__(128) uint4 g_pub[2 * NVEC * VEC_STRIDE];

// ---- asm helpers
__device__ __forceinline__ uint4 ldv4u(const uint4* p) {
    uint4 v;
    asm volatile("ld.volatile.global.v4.u32 {%0,%1,%2,%3}, [%4];"
                 : "=r"(v.x), "=r"(v.y), "=r"(v.z), "=r"(v.w) : "l"(p));
    return v;
}
__device__ __forceinline__ void stv4u(uint4* p, uint4 v) {
    asm volatile("st.volatile.global.v4.u32 [%0], {%1,%2,%3,%4};"
                 :: "l"(p), "r"(v.x), "r"(v.y), "r"(v.z), "r"(v.w) : "memory");
}
__device__ __forceinline__ uint32_t pack_bf16(float lo, float hi) {
    __nv_bfloat162 v = __floats2bfloat162_rn(lo, hi);
    return *reinterpret_cast<uint32_t*>(&v);
}
__device__ __forceinline__ float bf16lo(uint32_t u) { return __uint_as_float(u << 16); }
__device__ __forceinline__ float bf16hi(uint32_t u) { return __uint_as_float(u & 0xFFFF0000u); }
__device__ __forceinline__ void cp16(uint32_t sdst, const void* gsrc) {
    asm volatile("cp.async.cg.shared.global [%0], [%1], 16;\n" :: "r"(sdst), "l"(gsrc));
}
__device__ __forceinline__ void cp_commit() { asm volatile("cp.async.commit_group;\n"); }
__device__ __forceinline__ void cp_wait0()  { asm volatile("cp.async.wait_group 0;\n"); }
__device__ __forceinline__ void mma_bf16(float d[4], const uint32_t a[4], const uint32_t b[2]) {
    asm volatile(
        "mma.sync.aligned.m16n8k16.row.col.f32.bf16.bf16.f32 "
        "{%0,%1,%2,%3}, {%4,%5,%6,%7}, {%8,%9}, {%0,%1,%2,%3};\n"
        : "+f"(d[0]), "+f"(d[1]), "+f"(d[2]), "+f"(d[3])
        : "r"(a[0]), "r"(a[1]), "r"(a[2]), "r"(a[3]), "r"(b[0]), "r"(b[1]));
}
__device__ __forceinline__ void ldsm_x4(uint32_t& r0, uint32_t& r1, uint32_t& r2, uint32_t& r3,
                                        uint32_t saddr) {
    asm volatile("ldmatrix.sync.aligned.m8n8.x4.shared.b16 {%0,%1,%2,%3}, [%4];"
                 : "=r"(r0), "=r"(r1), "=r"(r2), "=r"(r3) : "r"(saddr));
}

// ---------------- init: clear exchange tags each launch
__global__ void init_kernel() {
    int i = blockIdx.x * blockDim.x + threadIdx.x;
    if (i < 2 * NVEC) g_pub[i * VEC_STRIDE].w = 0u;
}

// ---------------- phase 1: recurrence (R11 WIN design, gather folded)
__global__ void __launch_bounds__(RNN_THREADS, 1)
rnn_steps_kernel(const int* __restrict__ chars,
                 const float* __restrict__ Wxh,
                 const float* __restrict__ Whh,
                 const float* __restrict__ bh,
                 const float* __restrict__ h0) {
    __shared__ float    sh[HDIM];
    __shared__ uint32_t hout_u[8];
    __shared__ int      s_chars[TSTEPS];

    const int tid  = threadIdx.x;
    const int wid  = tid >> 5;
    const int lane = tid & 31;
    const int r0   = blockIdx.x * 16 + wid * 2;
    const int r1   = r0 + 1;

    float4 w0[8], w1[8];
    {
        const float4* p0 = reinterpret_cast<const float4*>(Whh + (size_t)r0 * HDIM);
        const float4* p1 = reinterpret_cast<const float4*>(Whh + (size_t)r1 * HDIM);
#pragma unroll
        for (int j = 0; j < 8; ++j) { w0[j] = p0[j * 32 + lane]; w1[j] = p1[j * 32 + lane]; }
    }

    s_chars[tid] = chars[tid];
    reinterpret_cast<float4*>(sh)[tid] = reinterpret_cast<const float4*>(h0)[tid];
    __syncthreads();

    float bh0 = 0.f, bh1 = 0.f, px0 = 0.f, px1 = 0.f;
    if (lane == 0) {
        bh0 = bh[r0]; bh1 = bh[r1];
        const int c0 = s_chars[0];
        px0 = Wxh[(size_t)r0 * VOCAB + c0];
        px1 = Wxh[(size_t)r1 * VOCAB + c0];
    }

    for (int t = 0; t < TSTEPS; ++t) {
        float x0 = px0, x1 = px1;
        if (lane == 0 && t + 1 < TSTEPS) {
            const int cn = s_chars[t + 1];
            px0 = Wxh[(size_t)r0 * VOCAB + cn];
            px1 = Wxh[(size_t)r1 * VOCAB + cn];
        }

        float a0 = 0.f, a1 = 0.f;
#pragma unroll
        for (int j = 0; j < 8; ++j) {
            float4 hv = reinterpret_cast<const float4*>(sh)[j * 32 + lane];
            a0 += w0[j].x * hv.x + w0[j].y * hv.y + w0[j].z * hv.z + w0[j].w * hv.w;
            a1 += w1[j].x * hv.x + w1[j].y * hv.y + w1[j].z * hv.z + w1[j].w * hv.w;
        }
#pragma unroll
        for (int o = 16; o > 0; o >>= 1) {
            a0 += __shfl_down_sync(0xffffffffu, a0, o);
            a1 += __shfl_down_sync(0xffffffffu, a1, o);
        }

        if (lane == 0) {
            float h0v = tanhf(a0 + x0 + bh0);
            float h1v = tanhf(a1 + x1 + bh1);
            uint32_t pk = pack_bf16(h0v, h1v);
            *reinterpret_cast<uint32_t*>(g_Hb + (size_t)t * HDIM + r0) = pk;
            hout_u[wid] = pk;
        }

        if (t + 1 < TSTEPS) {
            const uint32_t tag = (uint32_t)(t + 1);
            __syncthreads();

            if (tid < VEC_PER_BLK) {
                const int j = tid;
                uint4 v;
                v.x = hout_u[3 * j];
                v.y = hout_u[(3 * j + 1 < 8) ? 3 * j + 1 : 7];
                v.z = hout_u[(3 * j + 2 < 8) ? 3 * j + 2 : 7];
                v.w = tag;
                stv4u(&g_pub[((t & 1) * NVEC + blockIdx.x * VEC_PER_BLK + j) * VEC_STRIDE], v);
            }

            if (tid < NVEC) {
                const uint4* base = &g_pub[(t & 1) * NVEC * VEC_STRIDE];
                uint4 v;
                do { v = ldv4u(base + tid * VEC_STRIDE); } while (v.w != tag);
                const int b = tid / VEC_PER_BLK, j = tid % VEC_PER_BLK;
                const int bs = b * 16, w0i = 3 * j;
                sh[bs + 2 * w0i]     = bf16lo(v.x);
                sh[bs + 2 * w0i + 1] = bf16hi(v.x);
                if (w0i + 1 < 8) {
                    sh[bs + 2 * w0i + 2] = bf16lo(v.y);
                    sh[bs + 2 * w0i + 3] = bf16hi(v.y);
                }
                if (w0i + 2 < 8) {
                    sh[bs + 2 * w0i + 4] = bf16lo(v.z);
                    sh[bs + 2 * w0i + 5] = bf16hi(v.z);
                }
            }
            __syncthreads();
        }
    }
}

// ---------------- phase 2: bf16 mma GEMM, 8 warps, 64x64 warp tiles
// (2m x 4n warp grid -> fragment smem re-reads cut from 96KB to 64KB per k-tile)
#define BM 128
#define BN 256
#define BK 32
#define GEMM_THREADS 256
#define PITCH_H 40
#define A_TILE_H (BM * PITCH_H)
#define B_TILE_H (BN * PITCH_H)
#define STAGE_H  (A_TILE_H + B_TILE_H)
#define GEMM_SMEM_BYTES (2 * STAGE_H * 2)     // 61440 B

extern __shared__ __nv_bfloat16 g_smem[];

__global__ void __launch_bounds__(GEMM_THREADS, 1)
gemm_logits_kernel(const float* __restrict__ Why,
                   const float* __restrict__ by,
                   float* __restrict__ out) {
    const int tid  = threadIdx.x;
    const int lane = tid & 31;
    const int wid  = tid >> 5;          // 0..7
    const int wm   = wid & 1;           // 2 m-groups -> 64 vocab rows each
    const int wn   = wid >> 1;          // 4 n-groups -> 64 time cols each
    const int m0   = blockIdx.x * BM;

    const uint32_t smem_u = (uint32_t)__cvta_generic_to_shared(g_smem);

    // A (Why) LDG mapping: 2 threads per row, 16 fp32 each
    const int arow = tid >> 1;          // 0..127
    const int ahalf = tid & 1;          // k-half: 0 or 16 floats
    int agm = m0 + arow; if (agm > VOCAB - 1) agm = VOCAB - 1;
    const float4* Aptr = reinterpret_cast<const float4*>(Why + (size_t)agm * HDIM) + ahalf * 4;

    // B loader: 256 rows x 4 chunks of 16B = 1024 ops -> 4 per thread
    auto load_B = [&](int stage, int k0) {
        uint32_t sb = smem_u + (uint32_t)(stage * STAGE_H + A_TILE_H) * 2u;
#pragma unroll
        for (int q = 0; q < 4; ++q) {
            int i = tid + q * GEMM_THREADS;
            int row = i >> 2, ch = i & 3;
            cp16(sb + (uint32_t)(row * PITCH_H + ch * 8) * 2u,
                 g_Hb + (size_t)row * HDIM + k0 + ch * 8);
        }
        cp_commit();
    };

    float acc[4][8][4] = {};

    float4 fa[4];
#pragma unroll
    for (int j = 0; j < 4; ++j) fa[j] = Aptr[j];
    load_B(0, 0);

    const int lra = lane & 15;
    const int lca = (lane >> 4) * 8;
    const int lrb = (lane & 7) + ((lane >> 4) * 8);
    const int lcb = ((lane >> 3) & 1) * 8;

    for (int kt = 0; kt < HDIM / BK; ++kt) {
        const int cur = kt & 1;
        __nv_bfloat16* As = g_smem + cur * STAGE_H;
        const uint32_t As_u = smem_u + (uint32_t)(cur * STAGE_H) * 2u;
        const uint32_t Bs_u = As_u + (uint32_t)A_TILE_H * 2u;

        {   // STS this kt's A: 16 floats -> 2x STS.128
            uint4 p;
            p.x = pack_bf16(fa[0].x, fa[0].y); p.y = pack_bf16(fa[0].z, fa[0].w);
            p.z = pack_bf16(fa[1].x, fa[1].y); p.w = pack_bf16(fa[1].z, fa[1].w);
            *reinterpret_cast<uint4*>(As + arow * PITCH_H + ahalf * 16) = p;
            uint4 p2;
            p2.x = pack_bf16(fa[2].x, fa[2].y); p2.y = pack_bf16(fa[2].z, fa[2].w);
            p2.z = pack_bf16(fa[3].x, fa[3].y); p2.w = pack_bf16(fa[3].z, fa[3].w);
            *reinterpret_cast<uint4*>(As + arow * PITCH_H + ahalf * 16 + 8) = p2;
        }
        if (kt + 1 < HDIM / BK) {
            const float4* An = Aptr + (kt + 1) * 8;
#pragma unroll
            for (int j = 0; j < 4; ++j) fa[j] = An[j];
        }

        cp_wait0();
        __syncthreads();

        if (kt + 1 < HDIM / BK)
            load_B(cur ^ 1, (kt + 1) * BK);

#pragma unroll
        for (int ki = 0; ki < 2; ++ki) {
            const int kk = ki * 16;
            uint32_t a[4][4], b[8][2];
#pragma unroll
            for (int mi = 0; mi < 4; ++mi)
                ldsm_x4(a[mi][0], a[mi][1], a[mi][2], a[mi][3],
                        As_u + (uint32_t)((wm * 64 + mi * 16 + lra) * PITCH_H + kk + lca) * 2u);
#pragma unroll
            for (int nf2 = 0; nf2 < 4; ++nf2)
                ldsm_x4(b[2 * nf2][0], b[2 * nf2][1], b[2 * nf2 + 1][0], b[2 * nf2 + 1][1],
                        Bs_u + (uint32_t)((wn * 64 + nf2 * 16 + lrb) * PITCH_H + kk + lcb) * 2u);
#pragma unroll
            for (int mi = 0; mi < 4; ++mi)
#pragma unroll
                for (int nf = 0; nf < 8; ++nf)
                    mma_bf16(acc[mi][nf], a[mi], b[nf]);
        }
    }

    // ---- epilogue: out[t][v] = acc + by[v]
    const int r = lane >> 2;
    const int c = lane & 3;
#pragma unroll
    for (int mi = 0; mi < 4; ++mi) {
        const int v0 = m0 + wm * 64 + mi * 16 + r;
        const int v1 = v0 + 8;
        const float bias0 = (v0 < VOCAB) ? by[v0] : 0.f;
        const float bias1 = (v1 < VOCAB) ? by[v1] : 0.f;
#pragma unroll
        for (int nf = 0; nf < 8; ++nf) {
            const int t0 = wn * 64 + nf * 8 + c * 2;
            const int t1 = t0 + 1;
            if (v0 < VOCAB) {
                out[(size_t)t0 * VOCAB + v0] = acc[mi][nf][0] + bias0;
                out[(size_t)t1 * VOCAB + v0] = acc[mi][nf][1] + bias0;
            }
            if (v1 < VOCAB) {
                out[(size_t)t0 * VOCAB + v1] = acc[mi][nf][2] + bias1;
                out[(size_t)t1 * VOCAB + v1] = acc[mi][nf][3] + bias1;
            }
        }
    }
}

// ---------------- phase 3: softmax, no max pass (logits bounded ~|1|), smem exp cache
#define SMAX_SMEM_BYTES (VOCAB * 4)

extern __shared__ float s_exp[];

__global__ void __launch_bounds__(1024) softmax_rows_kernel(float* __restrict__ out) {
    __shared__ float red[1024];
    const int t = blockIdx.x;
    float* row = out + (size_t)t * VOCAB;
    const int tid = threadIdx.x;

    float sum = 0.f;
    for (int i = tid; i < VOCAB; i += 1024) {
        float e = expf(row[i]);
        s_exp[i] = e;
        sum += e;
    }
    red[tid] = sum; __syncthreads();
    for (int s = 512; s > 0; s >>= 1) {
        if (tid < s) red[tid] += red[tid + s];
        __syncthreads();
    }
    const float inv = 1.0f / red[0];
    __syncthreads();

    for (int i = tid; i < VOCAB; i += 1024) row[i] = s_exp[i] * inv;
}

// ---------------- launch ----------------
extern "C" void kernel_launch(void* const* d_in, const int* in_sizes, int n_in,
                              void* d_out, int out_size) {
    const int*   chars = (const int*)  d_in[0];
    const float* Wxh   = (const float*)d_in[1];
    const float* Whh   = (const float*)d_in[2];
    const float* Why   = (const float*)d_in[3];
    const float* bh    = (const float*)d_in[4];
    const float* by    = (const float*)d_in[5];
    const float* h0    = (const float*)d_in[6];
    float* out = (float*)d_out;

    cudaFuncSetAttribute(gemm_logits_kernel,
                         cudaFuncAttributeMaxDynamicSharedMemorySize, GEMM_SMEM_BYTES);
    cudaFuncSetAttribute(softmax_rows_kernel,
                         cudaFuncAttributeMaxDynamicSharedMemorySize, SMAX_SMEM_BYTES);

    init_kernel<<<1, 512>>>();
    rnn_steps_kernel<<<RNN_NB, RNN_THREADS>>>(chars, Wxh, Whh, bh, h0);
    gemm_logits_kernel<<<(VOCAB + BM - 1) / BM, GEMM_THREADS, GEMM_SMEM_BYTES>>>(Why, by, out);
    softmax_rows_kernel<<<TSTEPS, 1024, SMAX_SMEM_BYTES>>>(out);
}

// round 13
// speedup vs baseline: 1.0599x; 1.0599x over previous
#include <cuda_runtime.h>
#include <cuda_bf16.h>
#include <math.h>
#include <stdint.h>

#define HDIM   1024
#define TSTEPS 256
#define VOCAB  50257
#define VBLKS  ((VOCAB + 127) / 128)         // 393

// ---------------- recurrence config (R11 WIN, untouched) ----------------
#define RNN_NB      64
#define RNN_THREADS 256
#define VEC_PER_BLK 3
#define NVEC        (RNN_NB * VEC_PER_BLK)   // 192
#define VEC_STRIDE  8                        // 128B per vector

// -------- device scratch --------
__device__ __align__(16)  __nv_bfloat16 g_Hb[TSTEPS * HDIM];
__device__ __align__(128) uint4 g_pub[2 * NVEC * VEC_STRIDE];
__device__ __align__(16)  float g_psum[TSTEPS * VBLKS];   // exp partial sums [t][vb]

// ---- asm helpers
__device__ __forceinline__ uint4 ldv4u(const uint4* p) {
    uint4 v;
    asm volatile("ld.volatile.global.v4.u32 {%0,%1,%2,%3}, [%4];"
                 : "=r"(v.x), "=r"(v.y), "=r"(v.z), "=r"(v.w) : "l"(p));
    return v;
}
__device__ __forceinline__ void stv4u(uint4* p, uint4 v) {
    asm volatile("st.volatile.global.v4.u32 [%0], {%1,%2,%3,%4};"
                 :: "l"(p), "r"(v.x), "r"(v.y), "r"(v.z), "r"(v.w) : "memory");
}
__device__ __forceinline__ uint32_t pack_bf16(float lo, float hi) {
    __nv_bfloat162 v = __floats2bfloat162_rn(lo, hi);
    return *reinterpret_cast<uint32_t*>(&v);
}
__device__ __forceinline__ float bf16lo(uint32_t u) { return __uint_as_float(u << 16); }
__device__ __forceinline__ float bf16hi(uint32_t u) { return __uint_as_float(u & 0xFFFF0000u); }
__device__ __forceinline__ void cp16(uint32_t sdst, const void* gsrc) {
    asm volatile("cp.async.cg.shared.global [%0], [%1], 16;\n" :: "r"(sdst), "l"(gsrc));
}
__device__ __forceinline__ void cp_commit() { asm volatile("cp.async.commit_group;\n"); }
__device__ __forceinline__ void cp_wait0()  { asm volatile("cp.async.wait_group 0;\n"); }
__device__ __forceinline__ void mma_bf16(float d[4], const uint32_t a[4], const uint32_t b[2]) {
    asm volatile(
        "mma.sync.aligned.m16n8k16.row.col.f32.bf16.bf16.f32 "
        "{%0,%1,%2,%3}, {%4,%5,%6,%7}, {%8,%9}, {%0,%1,%2,%3};\n"
        : "+f"(d[0]), "+f"(d[1]), "+f"(d[2]), "+f"(d[3])
        : "r"(a[0]), "r"(a[1]), "r"(a[2]), "r"(a[3]), "r"(b[0]), "r"(b[1]));
}
__device__ __forceinline__ void ldsm_x4(uint32_t& r0, uint32_t& r1, uint32_t& r2, uint32_t& r3,
                                        uint32_t saddr) {
    asm volatile("ldmatrix.sync.aligned.m8n8.x4.shared.b16 {%0,%1,%2,%3}, [%4];"
                 : "=r"(r0), "=r"(r1), "=r"(r2), "=r"(r3) : "r"(saddr));
}

// ---------------- init: clear exchange tags each launch
__global__ void init_kernel() {
    int i = blockIdx.x * blockDim.x + threadIdx.x;
    if (i < 2 * NVEC) g_pub[i * VEC_STRIDE].w = 0u;
}

// ---------------- phase 1: recurrence (R11 WIN design, gather folded)
__global__ void __launch_bounds__(RNN_THREADS, 1)
rnn_steps_kernel(const int* __restrict__ chars,
                 const float* __restrict__ Wxh,
                 const float* __restrict__ Whh,
                 const float* __restrict__ bh,
                 const float* __restrict__ h0) {
    __shared__ float    sh[HDIM];
    __shared__ uint32_t hout_u[8];
    __shared__ int      s_chars[TSTEPS];

    const int tid  = threadIdx.x;
    const int wid  = tid >> 5;
    const int lane = tid & 31;
    const int r0   = blockIdx.x * 16 + wid * 2;
    const int r1   = r0 + 1;

    float4 w0[8], w1[8];
    {
        const float4* p0 = reinterpret_cast<const float4*>(Whh + (size_t)r0 * HDIM);
        const float4* p1 = reinterpret_cast<const float4*>(Whh + (size_t)r1 * HDIM);
#pragma unroll
        for (int j = 0; j < 8; ++j) { w0[j] = p0[j * 32 + lane]; w1[j] = p1[j * 32 + lane]; }
    }

    s_chars[tid] = chars[tid];
    reinterpret_cast<float4*>(sh)[tid] = reinterpret_cast<const float4*>(h0)[tid];
    __syncthreads();

    float bh0 = 0.f, bh1 = 0.f, px0 = 0.f, px1 = 0.f;
    if (lane == 0) {
        bh0 = bh[r0]; bh1 = bh[r1];
        const int c0 = s_chars[0];
        px0 = Wxh[(size_t)r0 * VOCAB + c0];
        px1 = Wxh[(size_t)r1 * VOCAB + c0];
    }

    for (int t = 0; t < TSTEPS; ++t) {
        float x0 = px0, x1 = px1;
        if (lane == 0 && t + 1 < TSTEPS) {
            const int cn = s_chars[t + 1];
            px0 = Wxh[(size_t)r0 * VOCAB + cn];
            px1 = Wxh[(size_t)r1 * VOCAB + cn];
        }

        float a0 = 0.f, a1 = 0.f;
#pragma unroll
        for (int j = 0; j < 8; ++j) {
            float4 hv = reinterpret_cast<const float4*>(sh)[j * 32 + lane];
            a0 += w0[j].x * hv.x + w0[j].y * hv.y + w0[j].z * hv.z + w0[j].w * hv.w;
            a1 += w1[j].x * hv.x + w1[j].y * hv.y + w1[j].z * hv.z + w1[j].w * hv.w;
        }
#pragma unroll
        for (int o = 16; o > 0; o >>= 1) {
            a0 += __shfl_down_sync(0xffffffffu, a0, o);
            a1 += __shfl_down_sync(0xffffffffu, a1, o);
        }

        if (lane == 0) {
            float h0v = tanhf(a0 + x0 + bh0);
            float h1v = tanhf(a1 + x1 + bh1);
            uint32_t pk = pack_bf16(h0v, h1v);
            *reinterpret_cast<uint32_t*>(g_Hb + (size_t)t * HDIM + r0) = pk;
            hout_u[wid] = pk;
        }

        if (t + 1 < TSTEPS) {
            const uint32_t tag = (uint32_t)(t + 1);
            __syncthreads();

            if (tid < VEC_PER_BLK) {
                const int j = tid;
                uint4 v;
                v.x = hout_u[3 * j];
                v.y = hout_u[(3 * j + 1 < 8) ? 3 * j + 1 : 7];
                v.z = hout_u[(3 * j + 2 < 8) ? 3 * j + 2 : 7];
                v.w = tag;
                stv4u(&g_pub[((t & 1) * NVEC + blockIdx.x * VEC_PER_BLK + j) * VEC_STRIDE], v);
            }

            if (tid < NVEC) {
                const uint4* base = &g_pub[(t & 1) * NVEC * VEC_STRIDE];
                uint4 v;
                do { v = ldv4u(base + tid * VEC_STRIDE); } while (v.w != tag);
                const int b = tid / VEC_PER_BLK, j = tid % VEC_PER_BLK;
                const int bs = b * 16, w0i = 3 * j;
                sh[bs + 2 * w0i]     = bf16lo(v.x);
                sh[bs + 2 * w0i + 1] = bf16hi(v.x);
                if (w0i + 1 < 8) {
                    sh[bs + 2 * w0i + 2] = bf16lo(v.y);
                    sh[bs + 2 * w0i + 3] = bf16hi(v.y);
                }
                if (w0i + 2 < 8) {
                    sh[bs + 2 * w0i + 4] = bf16lo(v.z);
                    sh[bs + 2 * w0i + 5] = bf16hi(v.z);
                }
            }
            __syncthreads();
        }
    }
}

// ---------------- phase 2: bf16 mma GEMM (R11 16-warp layout) + exp epilogue
// out[t][v] = exp(logits[t][v] + by[v]); g_psum[t][vb] = partial row sums.
#define BM 128
#define BN 256
#define BK 32
#define GEMM_THREADS 512
#define PITCH_H 40
#define A_TILE_H (BM * PITCH_H)
#define B_TILE_H (BN * PITCH_H)
#define STAGE_H  (A_TILE_H + B_TILE_H)
#define GEMM_SMEM_BYTES (2 * STAGE_H * 2)     // 61440 B

extern __shared__ __nv_bfloat16 g_smem[];

__global__ void __launch_bounds__(GEMM_THREADS, 1)
gemm_logits_kernel(const float* __restrict__ Why,
                   const float* __restrict__ by,
                   float* __restrict__ out) {
    __shared__ float ps[4][TSTEPS];   // per-wm partial sums, deterministic

    const int tid  = threadIdx.x;
    const int lane = tid & 31;
    const int wid  = tid >> 5;
    const int wm   = wid & 3;        // warp m (0..3) -> 32 vocab rows
    const int wn   = wid >> 2;       // warp n (0..3) -> 64 time cols
    const int m0   = blockIdx.x * BM;

    const uint32_t smem_u = (uint32_t)__cvta_generic_to_shared(g_smem);

    const int arow = tid >> 2;
    const int ak0  = (tid & 3) * 8;
    int agm = m0 + arow; if (agm > VOCAB - 1) agm = VOCAB - 1;
    const float4* Aptr = reinterpret_cast<const float4*>(Why + (size_t)agm * HDIM + ak0);

    auto load_B = [&](int stage, int k0) {
        uint32_t sb = smem_u + (uint32_t)(stage * STAGE_H + A_TILE_H) * 2u;
#pragma unroll
        for (int q = 0; q < 2; ++q) {
            int i = tid + q * GEMM_THREADS;
            int row = i >> 2, ch = i & 3;
            cp16(sb + (uint32_t)(row * PITCH_H + ch * 8) * 2u,
                 g_Hb + (size_t)row * HDIM + k0 + ch * 8);
        }
        cp_commit();
    };

    float acc[2][8][4] = {};

    float4 fa = Aptr[0];
    float4 fb = Aptr[1];
    load_B(0, 0);

    const int lra = lane & 15;
    const int lca = (lane >> 4) * 8;
    const int lrb = (lane & 7) + ((lane >> 4) * 8);
    const int lcb = ((lane >> 3) & 1) * 8;

    for (int kt = 0; kt < HDIM / BK; ++kt) {
        const int cur = kt & 1;
        __nv_bfloat16* As = g_smem + cur * STAGE_H;
        const uint32_t As_u = smem_u + (uint32_t)(cur * STAGE_H) * 2u;
        const uint32_t Bs_u = As_u + (uint32_t)A_TILE_H * 2u;

        {
            uint4 p;
            p.x = pack_bf16(fa.x, fa.y);
            p.y = pack_bf16(fa.z, fa.w);
            p.z = pack_bf16(fb.x, fb.y);
            p.w = pack_bf16(fb.z, fb.w);
            *reinterpret_cast<uint4*>(As + arow * PITCH_H + ak0) = p;
        }
        if (kt + 1 < HDIM / BK) {
            const float4* An = Aptr + (kt + 1) * (BK / 4);
            fa = An[0];
            fb = An[1];
        }

        cp_wait0();
        __syncthreads();

        if (kt + 1 < HDIM / BK)
            load_B(cur ^ 1, (kt + 1) * BK);

#pragma unroll
        for (int ki = 0; ki < 2; ++ki) {
            const int kk = ki * 16;
            uint32_t a[2][4], b[8][2];
#pragma unroll
            for (int mi = 0; mi < 2; ++mi)
                ldsm_x4(a[mi][0], a[mi][1], a[mi][2], a[mi][3],
                        As_u + (uint32_t)((wm * 32 + mi * 16 + lra) * PITCH_H + kk + lca) * 2u);
#pragma unroll
            for (int nf2 = 0; nf2 < 4; ++nf2)
                ldsm_x4(b[2 * nf2][0], b[2 * nf2][1], b[2 * nf2 + 1][0], b[2 * nf2 + 1][1],
                        Bs_u + (uint32_t)((wn * 64 + nf2 * 16 + lrb) * PITCH_H + kk + lcb) * 2u);
#pragma unroll
            for (int mi = 0; mi < 2; ++mi)
#pragma unroll
                for (int nf = 0; nf < 8; ++nf)
                    mma_bf16(acc[mi][nf], a[mi], b[nf]);
        }
    }

    // zero partial-sum array
    __syncthreads();
    for (int i = tid; i < 4 * TSTEPS; i += GEMM_THREADS)
        reinterpret_cast<float*>(ps)[i] = 0.f;
    __syncthreads();

    // ---- epilogue: e = exp(acc + by); store; deterministic partial sums
    const int r = lane >> 2;
    const int c = lane & 3;
#pragma unroll
    for (int nf = 0; nf < 8; ++nf) {
        const int t0 = wn * 64 + nf * 8 + c * 2;
        const int t1 = t0 + 1;
        float s0 = 0.f, s1 = 0.f;
#pragma unroll
        for (int mi = 0; mi < 2; ++mi) {
            const int v0 = m0 + wm * 32 + mi * 16 + r;
            const int v1 = v0 + 8;
            if (v0 < VOCAB) {
                const float bias0 = by[v0];
                float e00 = expf(acc[mi][nf][0] + bias0);
                float e01 = expf(acc[mi][nf][1] + bias0);
                out[(size_t)t0 * VOCAB + v0] = e00;
                out[(size_t)t1 * VOCAB + v0] = e01;
                s0 += e00; s1 += e01;
            }
            if (v1 < VOCAB) {
                const float bias1 = by[v1];
                float e02 = expf(acc[mi][nf][2] + bias1);
                float e03 = expf(acc[mi][nf][3] + bias1);
                out[(size_t)t0 * VOCAB + v1] = e02;
                out[(size_t)t1 * VOCAB + v1] = e03;
                s0 += e02; s1 += e03;
            }
        }
        // reduce over r-groups (lanes differing by 4)
#pragma unroll
        for (int o = 16; o >= 4; o >>= 1) {
            s0 += __shfl_down_sync(0xffffffffu, s0, o);
            s1 += __shfl_down_sync(0xffffffffu, s1, o);
        }
        if (lane < 4 && lane == c) {   // lanes 0..3 hold c=lane sums
            ps[wm][wn * 64 + nf * 8 + lane * 2]     = s0;
            ps[wm][wn * 64 + nf * 8 + lane * 2 + 1] = s1;
        }
    }
    __syncthreads();
    if (tid < TSTEPS)
        g_psum[(size_t)tid * VBLKS + blockIdx.x] =
            ps[0][tid] + ps[1][tid] + ps[2][tid] + ps[3][tid];
}

// ---------------- phase 3: normalize rows: out[t][:] *= 1/sum(exp)
__global__ void __launch_bounds__(1024) norm_rows_kernel(float* __restrict__ out) {
    __shared__ float red[1024];
    const int t = blockIdx.x;
    const int tid = threadIdx.x;

    float s = 0.f;
    for (int i = tid; i < VBLKS; i += 1024) s += g_psum[(size_t)t * VBLKS + i];
    red[tid] = s; __syncthreads();
    for (int st = 512; st > 0; st >>= 1) {
        if (tid < st) red[tid] += red[tid + st];
        __syncthreads();
    }
    const float inv = 1.0f / red[0];

    float* row = out + (size_t)t * VOCAB;
    for (int i = tid; i < VOCAB; i += 1024) row[i] *= inv;
}

// ---------------- launch ----------------
extern "C" void kernel_launch(void* const* d_in, const int* in_sizes, int n_in,
                              void* d_out, int out_size) {
    const int*   chars = (const int*)  d_in[0];
    const float* Wxh   = (const float*)d_in[1];
    const float* Whh   = (const float*)d_in[2];
    const float* Why   = (const float*)d_in[3];
    const float* bh    = (const float*)d_in[4];
    const float* by    = (const float*)d_in[5];
    const float* h0    = (const float*)d_in[6];
    float* out = (float*)d_out;

    cudaFuncSetAttribute(gemm_logits_kernel,
                         cudaFuncAttributeMaxDynamicSharedMemorySize, GEMM_SMEM_BYTES);

    init_kernel<<<1, 512>>>();
    rnn_steps_kernel<<<RNN_NB, RNN_THREADS>>>(chars, Wxh, Whh, bh, h0);
    gemm_logits_kernel<<<VBLKS, GEMM_THREADS, GEMM_SMEM_BYTES>>>(Why, by, out);
    norm_rows_kernel<<<TSTEPS, 1024>>>(out);
}